// round 1
// baseline (speedup 1.0000x reference)
#include <cuda_runtime.h>
#include <cstddef>

#define N_ROWS 32768
#define DIMS   64
#define RULES  32
#define JLEN   65            // 1 + DIMS
#define EPSV   1e-12f
#define WARPS  8
#define RPW    4             // rows per warp
#define ROWS_PER_BLOCK (WARPS * RPW)   // 32
#define PHI_F4 ((RULES * JLEN) / 4)    // 520 float4 per row

__global__ __launch_bounds__(256) void tsk_kernel(
    const float* __restrict__ Xz,
    const float* __restrict__ centers,
    const float* __restrict__ sigmas,
    const float* __restrict__ theta,
    float* __restrict__ out)
{
    // (inv_sigma, -center*inv_sigma), stride 65 -> conflict-free for lane=r
    __shared__ float2 s_pc[RULES * JLEN];
    __shared__ float  s_th[RULES * JLEN];
    __shared__ float  s_x1[WARPS][RPW][JLEN + 3];   // stride 68; x1[0] = 1
    __shared__ float  s_w [WARPS][RPW][RULES];

    const int tid  = threadIdx.x;
    const int warp = tid >> 5;
    const int lane = tid & 31;

    // ---- preprocess parameters into shared (once per block) ----
    for (int i = tid; i < RULES * DIMS; i += 256) {
        int r = i >> 6;           // i / 64
        int d = i & 63;
        float s   = sigmas[i];
        float inv = 1.0f / (s + EPSV);
        s_pc[r * JLEN + d] = make_float2(inv, -centers[i] * inv);
    }
    for (int i = tid; i < RULES * JLEN; i += 256) {
        s_th[i] = theta[i];       // theta is (R, 65) row-major: shared idx == flat idx
    }
    __syncthreads();

    float* __restrict__ y_out   = out;
    float* __restrict__ w_out   = out + N_ROWS;
    float* __restrict__ phi_out = out + N_ROWS + (size_t)N_ROWS * RULES;

    const int base = blockIdx.x * ROWS_PER_BLOCK + warp * RPW;

    // ---- load x for 4 rows into per-warp X1 arrays ----
    #pragma unroll
    for (int k = 0; k < RPW; k++) {
        int row = base + k;
        float a = Xz[row * DIMS + lane];
        float b = Xz[row * DIMS + 32 + lane];
        s_x1[warp][k][1 + lane]  = a;
        s_x1[warp][k][33 + lane] = b;
        if (lane == 0) s_x1[warp][k][0] = 1.0f;
    }
    __syncwarp();

    // ---- lane = rule: distance accumulation + theta dot, 4 rows at once ----
    float acc[RPW], dot[RPW];
    #pragma unroll
    for (int k = 0; k < RPW; k++) {
        acc[k] = 0.0f;
        dot[k] = s_th[lane * JLEN];    // bias theta[r][0]
    }

    #pragma unroll 4
    for (int d = 0; d < DIMS; d++) {
        float2 p = s_pc[lane * JLEN + d];        // (inv, -c*inv)
        float  t = s_th[lane * JLEN + d + 1];
        #pragma unroll
        for (int k = 0; k < RPW; k++) {
            float xd = s_x1[warp][k][1 + d];     // broadcast
            float z  = fmaf(xd, p.x, p.y);       // (x - c) * inv
            acc[k] = fmaf(z, z, acc[k]);
            dot[k] = fmaf(t, xd, dot[k]);
        }
    }

    // ---- softmax over rules (lanes) + y reduction + w writeback ----
    #pragma unroll
    for (int k = 0; k < RPW; k++) {
        float lw = -0.5f * acc[k];
        float m = lw;
        #pragma unroll
        for (int o = 16; o > 0; o >>= 1)
            m = fmaxf(m, __shfl_xor_sync(0xffffffffu, m, o));
        float e = __expf(lw - m);
        float s = e;
        #pragma unroll
        for (int o = 16; o > 0; o >>= 1)
            s += __shfl_xor_sync(0xffffffffu, s, o);
        float wv = e * (1.0f / (s + EPSV));

        s_w[warp][k][lane] = wv;
        int row = base + k;
        w_out[(size_t)row * RULES + lane] = wv;   // coalesced 128B per row

        float yv = wv * dot[k];
        #pragma unroll
        for (int o = 16; o > 0; o >>= 1)
            yv += __shfl_xor_sync(0xffffffffu, yv, o);
        if (lane == 0) y_out[row] = yv;
    }
    __syncwarp();

    // ---- Phi: coalesced float4 stream, val = w[r] * x1[j] (x1[0]==1) ----
    #pragma unroll
    for (int k = 0; k < RPW; k++) {
        int row = base + k;
        float4* __restrict__ ph =
            reinterpret_cast<float4*>(phi_out + (size_t)row * (RULES * JLEN));
        const float* __restrict__ x1 = s_x1[warp][k];
        const float* __restrict__ wl = s_w[warp][k];

        for (int q = lane; q < PHI_F4; q += 32) {
            int e = q * 4;
            int r = e / 65;
            int j = e - r * 65;
            float4 v;
            v.x = wl[r] * x1[j]; if (++j == 65) { j = 0; ++r; }
            v.y = wl[r] * x1[j]; if (++j == 65) { j = 0; ++r; }
            v.z = wl[r] * x1[j]; if (++j == 65) { j = 0; ++r; }
            v.w = wl[r] * x1[j];
            ph[q] = v;
        }
    }
}

extern "C" void kernel_launch(void* const* d_in, const int* in_sizes, int n_in,
                              void* d_out, int out_size)
{
    const float* Xz      = (const float*)d_in[0];
    const float* centers = (const float*)d_in[1];
    const float* sigmas  = (const float*)d_in[2];
    const float* theta   = (const float*)d_in[3];
    float* out = (float*)d_out;

    tsk_kernel<<<N_ROWS / ROWS_PER_BLOCK, 256>>>(Xz, centers, sigmas, theta, out);
}

// round 2
// speedup vs baseline: 1.0312x; 1.0312x over previous
#include <cuda_runtime.h>
#include <cstddef>

#define N_ROWS 32768
#define DIMS   64
#define RULES  32
#define JLEN   65            // 1 + DIMS
#define EPSV   1e-12f
#define WARPS  8
#define RPW    4             // rows per warp
#define ROWS_PER_BLOCK (WARPS * RPW)   // 32
#define PHI_F4 ((RULES * JLEN) / 4)    // 520 float4 per row
#define FULL   0xffffffffu

__global__ __launch_bounds__(256) void tsk_kernel(
    const float* __restrict__ Xz,
    const float* __restrict__ centers,
    const float* __restrict__ sigmas,
    const float* __restrict__ theta,
    float* __restrict__ out)
{
    // (inv_sigma, -center*inv_sigma) at float2 stride 65:
    // half-warp lanes hit 16 distinct even start-banks -> conflict-free LDS.64
    __shared__ float2 s_pc[RULES * JLEN];
    __shared__ float  s_th[RULES * JLEN];

    const int tid  = threadIdx.x;
    const int warp = tid >> 5;
    const int lane = tid & 31;

    // ---- preprocess parameters into shared (once per block) ----
    for (int i = tid; i < RULES * DIMS; i += 256) {
        int r = i >> 6;           // i / 64
        int d = i & 63;
        float s   = sigmas[i];
        float inv = 1.0f / (s + EPSV);
        s_pc[r * JLEN + d] = make_float2(inv, -centers[i] * inv);
    }
    for (int i = tid; i < RULES * JLEN; i += 256) {
        s_th[i] = theta[i];       // theta is (R, 65) row-major
    }
    __syncthreads();

    float* __restrict__ y_out   = out;
    float* __restrict__ w_out   = out + N_ROWS;
    float* __restrict__ phi_out = out + N_ROWS + (size_t)N_ROWS * RULES;

    const int base = blockIdx.x * ROWS_PER_BLOCK + warp * RPW;

    // ---- x for 4 rows lives entirely in registers ----
    float xa[RPW], xb[RPW];
    #pragma unroll
    for (int k = 0; k < RPW; k++) {
        int row = base + k;
        xa[k] = Xz[row * DIMS + lane];
        xb[k] = Xz[row * DIMS + 32 + lane];
    }

    // ---- lane = rule: distance accumulation + theta dot, 4 rows at once ----
    float acc[RPW], dot[RPW];
    #pragma unroll
    for (int k = 0; k < RPW; k++) {
        acc[k] = 0.0f;
        dot[k] = s_th[lane * JLEN];    // bias theta[r][0]
    }

    #pragma unroll 8
    for (int d = 0; d < DIMS; d++) {
        float2 p = s_pc[lane * JLEN + d];          // (inv, -c*inv)
        float  t = s_th[lane * JLEN + d + 1];
        #pragma unroll
        for (int k = 0; k < RPW; k++) {
            // d is uniform -> compile-time register select, 1 shfl
            float xd = __shfl_sync(FULL, (d < 32) ? xa[k] : xb[k], d & 31);
            float z  = fmaf(xd, p.x, p.y);         // (x - c) * inv
            acc[k] = fmaf(z, z, acc[k]);
            dot[k] = fmaf(t, xd, dot[k]);
        }
    }

    // ---- softmax over rules (lanes) + y reduction + w writeback ----
    float wk[RPW];
    #pragma unroll
    for (int k = 0; k < RPW; k++) {
        float lw = -0.5f * acc[k];
        float m = lw;
        #pragma unroll
        for (int o = 16; o > 0; o >>= 1)
            m = fmaxf(m, __shfl_xor_sync(FULL, m, o));
        float e = __expf(lw - m);
        float s = e;
        #pragma unroll
        for (int o = 16; o > 0; o >>= 1)
            s += __shfl_xor_sync(FULL, s, o);
        float wv = e * (1.0f / (s + EPSV));
        wk[k] = wv;

        int row = base + k;
        w_out[(size_t)row * RULES + lane] = wv;    // coalesced 128B per row

        float yv = wv * dot[k];
        #pragma unroll
        for (int o = 16; o > 0; o >>= 1)
            yv += __shfl_xor_sync(FULL, yv, o);
        if (lane == 0) y_out[row] = yv;
    }

    // ---- Phi: coalesced float4 stream; x1[j] and w[r] via shuffles ----
    // Fixed 17 iterations for every lane (no divergent shuffles); tail predicated.
    #pragma unroll
    for (int k = 0; k < RPW; k++) {
        int row = base + k;
        float4* __restrict__ ph =
            reinterpret_cast<float4*>(phi_out + (size_t)row * (RULES * JLEN));
        const float xak = xa[k];
        const float xbk = xb[k];
        const float wkk = wk[k];

        for (int it = 0; it < 17; ++it) {
            int q = it * 32 + lane;
            bool act = q < PHI_F4;
            int e = act ? (q << 2) : 0;
            int r = (e * 4033) >> 18;              // e / 65 for e < 2080
            int j = e - r * 65;

            // at most one rule boundary inside a float4: prefetch both weights
            float wv0 = __shfl_sync(FULL, wkk, r);
            float wv1 = __shfl_sync(FULL, wkk, (r < 31) ? (r + 1) : 31);

            float4 v;
            float* vp = &v.x;
            int  jj = j;
            bool wrapped = false;
            #pragma unroll
            for (int u = 0; u < 4; ++u) {
                int   idx = (jj - 1) & 31;
                float va  = __shfl_sync(FULL, xak, idx);
                float vb  = __shfl_sync(FULL, xbk, idx);
                float x1  = (jj == 0) ? 1.0f : ((jj <= 32) ? va : vb);
                float w   = wrapped ? wv1 : wv0;
                vp[u] = w * x1;
                if (++jj == JLEN) { jj = 0; wrapped = true; }
            }
            if (act) __stcs(&ph[q], v);            // streaming store
        }
    }
}

extern "C" void kernel_launch(void* const* d_in, const int* in_sizes, int n_in,
                              void* d_out, int out_size)
{
    const float* Xz      = (const float*)d_in[0];
    const float* centers = (const float*)d_in[1];
    const float* sigmas  = (const float*)d_in[2];
    const float* theta   = (const float*)d_in[3];
    float* out = (float*)d_out;

    tsk_kernel<<<N_ROWS / ROWS_PER_BLOCK, 256>>>(Xz, centers, sigmas, theta, out);
}

// round 4
// speedup vs baseline: 1.0982x; 1.0650x over previous
#include <cuda_runtime.h>
#include <cstddef>

#define N_ROWS 32768
#define DIMS   64
#define RULES  32
#define JLEN   65            // 1 + DIMS
#define EPSV   1e-12f
#define WARPS  8
#define RPW    4             // rows per warp
#define ROWS_PER_BLOCK (WARPS * RPW)   // 32
#define FULL   0xffffffffu

__global__ __launch_bounds__(256) void tsk_kernel(
    const float* __restrict__ Xz,
    const float* __restrict__ centers,
    const float* __restrict__ sigmas,
    const float* __restrict__ theta,
    float* __restrict__ out)
{
    // (inv_sigma, -center*inv_sigma) at float2 stride 65: conflict-free for lane=r
    __shared__ float2 s_pc[RULES * JLEN];
    __shared__ float  s_th[RULES * JLEN];

    const int tid  = threadIdx.x;
    const int warp = tid >> 5;
    const int lane = tid & 31;

    // ---- preprocess parameters into shared (once per block) ----
    for (int i = tid; i < RULES * DIMS; i += 256) {
        int r = i >> 6;           // i / 64
        int d = i & 63;
        float s   = sigmas[i];
        float inv = 1.0f / (s + EPSV);
        s_pc[r * JLEN + d] = make_float2(inv, -centers[i] * inv);
    }
    for (int i = tid; i < RULES * JLEN; i += 256) {
        s_th[i] = theta[i];       // theta is (R, 65) row-major
    }
    __syncthreads();

    float* __restrict__ y_out   = out;
    float* __restrict__ w_out   = out + N_ROWS;
    float* __restrict__ phi_out = out + N_ROWS + (size_t)N_ROWS * RULES;

    const int base = blockIdx.x * ROWS_PER_BLOCK + warp * RPW;

    // ---- x for 4 rows lives entirely in registers ----
    float xa[RPW], xb[RPW];
    #pragma unroll
    for (int k = 0; k < RPW; k++) {
        int row = base + k;
        xa[k] = Xz[row * DIMS + lane];
        xb[k] = Xz[row * DIMS + 32 + lane];
    }

    // ---- lane = rule: distance accumulation + theta dot, 4 rows at once ----
    float acc[RPW], dot[RPW];
    #pragma unroll
    for (int k = 0; k < RPW; k++) {
        acc[k] = 0.0f;
        dot[k] = s_th[lane * JLEN];    // bias theta[r][0]
    }

    #pragma unroll 8
    for (int d = 0; d < DIMS; d++) {
        float2 p = s_pc[lane * JLEN + d];          // (inv, -c*inv)
        float  t = s_th[lane * JLEN + d + 1];
        #pragma unroll
        for (int k = 0; k < RPW; k++) {
            // d is uniform -> compile-time register select, 1 shfl
            float xd = __shfl_sync(FULL, (d < 32) ? xa[k] : xb[k], d & 31);
            float z  = fmaf(xd, p.x, p.y);         // (x - c) * inv
            acc[k] = fmaf(z, z, acc[k]);
            dot[k] = fmaf(t, xd, dot[k]);
        }
    }

    // ---- softmax over rules (lanes) + y reduction + w writeback ----
    float wk[RPW];
    #pragma unroll
    for (int k = 0; k < RPW; k++) {
        float lw = -0.5f * acc[k];
        float m = lw;
        #pragma unroll
        for (int o = 16; o > 0; o >>= 1)
            m = fmaxf(m, __shfl_xor_sync(FULL, m, o));
        float e = __expf(lw - m);
        float s = e;
        #pragma unroll
        for (int o = 16; o > 0; o >>= 1)
            s += __shfl_xor_sync(FULL, s, o);
        float wv = e * (1.0f / (s + EPSV));
        wk[k] = wv;

        int row = base + k;
        w_out[(size_t)row * RULES + lane] = wv;    // coalesced 128B per row

        float yv = wv * dot[k];
        #pragma unroll
        for (int o = 16; o > 0; o >>= 1)
            yv += __shfl_xor_sync(FULL, yv, o);
        if (lane == 0) y_out[row] = yv;
    }

    // ---- Phi: per-rule register-direct stores ----
    // Segment for rule r: [w, w*x[0..31], w*x[32..63]] -> 1 scalar + 2 coalesced STG.
    // No index math, no variable shuffles, no shared traffic.
    #pragma unroll
    for (int k = 0; k < RPW; k++) {
        int row = base + k;
        float* __restrict__ ph = phi_out + (size_t)row * (RULES * JLEN);
        const float xak = xa[k];
        const float xbk = xb[k];
        const float wkk = wk[k];

        #pragma unroll
        for (int r = 0; r < RULES; r++) {
            float w = __shfl_sync(FULL, wkk, r);   // immediate lane index
            float* __restrict__ p = ph + r * JLEN;
            if (lane == 0) __stcs(p, w);
            __stcs(p + 1 + lane,  w * xak);
            __stcs(p + 33 + lane, w * xbk);
        }
    }
}

extern "C" void kernel_launch(void* const* d_in, const int* in_sizes, int n_in,
                              void* d_out, int out_size)
{
    const float* Xz      = (const float*)d_in[0];
    const float* centers = (const float*)d_in[1];
    const float* sigmas  = (const float*)d_in[2];
    const float* theta   = (const float*)d_in[3];
    float* out = (float*)d_out;

    tsk_kernel<<<N_ROWS / ROWS_PER_BLOCK, 256>>>(Xz, centers, sigmas, theta, out);
}